// round 5
// baseline (speedup 1.0000x reference)
#include <cuda_runtime.h>
#include <cstdint>
#include <math_constants.h>

// feat [N, C, 16, 8], scoremap [N, 13, 16, 8], conf [N, 13]
#define KP        13
#define HW        128       // 16*8 spatial
#define SPT       64        // total spatial pairs (f32x2 packing)
#define CPB       256       // channels per block (2 per thread)
#define THREADS   128
#define SPC       8         // spatial pairs per chunk
#define NCHUNK    (SPT / SPC)
#define FSTRIDE   258       // float2 per feat row; 258 % 16 == 2 -> STS.64 uniform 2-way,
                            // compute-side LDS.64 (consecutive lanes) conflict-free
#define SCS       18        // u64 per score smem row (13 pad to 18: 144B, 16B-aligned)

// ---------- f32x2 helpers (Blackwell packed fp32) ----------
__device__ __forceinline__ unsigned long long pack2(float a, float b) {
    unsigned long long r;
    asm("mov.b64 %0, {%1, %2};" : "=l"(r) : "f"(a), "f"(b));
    return r;
}
__device__ __forceinline__ float2 unpack2(unsigned long long v) {
    float2 f;
    asm("mov.b64 {%0, %1}, %2;" : "=f"(f.x), "=f"(f.y) : "l"(v));
    return f;
}
__device__ __forceinline__ unsigned long long fma2(unsigned long long a,
                                                   unsigned long long b,
                                                   unsigned long long c) {
    unsigned long long d;
    asm("fma.rn.f32x2 %0, %1, %2, %3;" : "=l"(d) : "l"(a), "l"(b), "l"(c));
    return d;
}
__device__ __forceinline__ unsigned long long add2(unsigned long long a,
                                                   unsigned long long b) {
    unsigned long long d;
    asm("add.rn.f32x2 %0, %1, %2;" : "=l"(d) : "l"(a), "l"(b));
    return d;
}

// smem: [ score: SPT x SCS u64 = 9216 B ][ feat: 2*SPC rows x FSTRIDE float2 = 16512 B ]
#define SMEM_BYTES (SPT * SCS * 8 + 2 * SPC * FSTRIDE * 8)

__global__ __launch_bounds__(THREADS, 4)
void horeid_kernel(const float* __restrict__ feat,
                   const float* __restrict__ score,
                   const float* __restrict__ conf,
                   float* __restrict__ out_feat,   // [N, 14, C]
                   float* __restrict__ out_conf,   // [N, 14]
                   int C)
{
    extern __shared__ unsigned char smem_raw[];
    unsigned long long* s_sc = (unsigned long long*)smem_raw;       // [SPT][SCS]
    float2* s_ft = (float2*)(smem_raw + SPT * SCS * 8);             // [2*SPC][FSTRIDE]

    const int tid = threadIdx.x;
    const int n   = blockIdx.y;
    const int c0  = blockIdx.x * CPB;

    // ---- tiny conf normalization, one thread of blockIdx.x==0 ----
    if (blockIdx.x == 0 && tid == 0) {
        const float* cp = conf + (size_t)n * KP;
        float s = 0.0f;
        #pragma unroll
        for (int k = 0; k < KP; k++) s += fabsf(cp[k]);
        s = fmaxf(s, 1e-12f);
        float* oc = out_conf + (size_t)n * (KP + 1);
        #pragma unroll
        for (int k = 0; k < KP; k++) oc[k] = cp[k] / s;
        oc[KP] = 1.0f;
    }

    // ---- stage all scoremap[n] once: s_sc[sp][k] = (score[k][2sp], score[k][2sp+1]) ----
    const float2* g_sc = (const float2*)(score + (size_t)n * KP * HW);
    #pragma unroll
    for (int i = tid; i < KP * SPT; i += THREADS) {
        int k  = i >> 6;          // 0..12
        int sp = i & 63;
        float2 v = g_sc[i];
        s_sc[sp * SCS + k] = pack2(v.x, v.y);
    }

    // ---- accumulators for 2 channels: cA = c0+tid, cB = cA+128 ----
    unsigned long long accA[KP], accB[KP];
    #pragma unroll
    for (int k = 0; k < KP; k++) { accA[k] = 0ull; accB[k] = 0ull; }
    unsigned long long sumA = 0ull, sumB = 0ull;
    float2 mxA = make_float2(-CUDART_INF_F, -CUDART_INF_F);
    float2 mxB = make_float2(-CUDART_INF_F, -CUDART_INF_F);

    const float4* g4 = (const float4*)(feat + ((size_t)n * C + c0) * HW);

    // Per chunk: 256 ch x 16 spatial = 1024 float4; 8 float4 per thread.
    // idx = tid + it*THREADS: cc = idx>>2 (channel), sqL = idx&3 (float4 in chunk).
    float4 v[8];
    #pragma unroll
    for (int it = 0; it < 8; it++) {
        int idx = tid + it * THREADS;
        v[it] = g4[(size_t)(idx >> 2) * (HW / 4) + (idx & 3)];     // chunk 0
    }

    for (int ch = 0; ch < NCHUNK; ch++) {
        if (ch) __syncthreads();               // prev chunk fully consumed

        // ---- store staged regs -> transposed [sp-pair][c] ----
        #pragma unroll
        for (int it = 0; it < 8; it++) {
            int idx = tid + it * THREADS;
            int cc  = idx >> 2;
            int sqL = idx & 3;
            s_ft[(2 * sqL    ) * FSTRIDE + cc] = make_float2(v[it].x, v[it].y);
            s_ft[(2 * sqL + 1) * FSTRIDE + cc] = make_float2(v[it].z, v[it].w);
        }
        __syncthreads();

        // ---- prefetch next chunk while computing this one ----
        if (ch < NCHUNK - 1) {
            #pragma unroll
            for (int it = 0; it < 8; it++) {
                int idx = tid + it * THREADS;
                v[it] = g4[(size_t)(idx >> 2) * (HW / 4) + ((ch + 1) * 4 + (idx & 3))];
            }
        }

        // ---- compute chunk: immediate smem offsets ----
        const unsigned long long* scb = s_sc + ch * SPC * SCS;
        #pragma unroll
        for (int spL = 0; spL < SPC; spL++) {
            float2 fa = s_ft[spL * FSTRIDE + tid];
            float2 fb = s_ft[spL * FSTRIDE + tid + (CPB / 2)];
            unsigned long long fda = pack2(fa.x, fa.y);
            unsigned long long fdb = pack2(fb.x, fb.y);

            const ulonglong2* srow = (const ulonglong2*)(scb + spL * SCS);
            #pragma unroll
            for (int j = 0; j < 6; j++) {              // k = 2j, 2j+1 via LDS.128
                ulonglong2 q = srow[j];
                accA[2 * j    ] = fma2(fda, q.x, accA[2 * j    ]);
                accB[2 * j    ] = fma2(fdb, q.x, accB[2 * j    ]);
                accA[2 * j + 1] = fma2(fda, q.y, accA[2 * j + 1]);
                accB[2 * j + 1] = fma2(fdb, q.y, accB[2 * j + 1]);
            }
            unsigned long long q12 = scb[spL * SCS + 12];
            accA[12] = fma2(fda, q12, accA[12]);
            accB[12] = fma2(fdb, q12, accB[12]);

            sumA = add2(sumA, fda);
            sumB = add2(sumB, fdb);
            mxA.x = fmaxf(mxA.x, fa.x); mxA.y = fmaxf(mxA.y, fa.y);
            mxB.x = fmaxf(mxB.x, fb.x); mxB.y = fmaxf(mxB.y, fb.y);
        }
    }

    // ---- epilogue: 13 local sums + (mean + max) global, for both channels ----
    const int cA = c0 + tid;
    const int cB = cA + (CPB / 2);
    float* op = out_feat + (size_t)n * (KP + 1) * C;
    #pragma unroll
    for (int k = 0; k < KP; k++) {
        float2 a = unpack2(accA[k]);
        float2 b = unpack2(accB[k]);
        op[(size_t)k * C + cA] = a.x + a.y;
        op[(size_t)k * C + cB] = b.x + b.y;
    }
    float2 sa = unpack2(sumA), sb = unpack2(sumB);
    op[(size_t)KP * C + cA] = (sa.x + sa.y) * (1.0f / (float)HW) + fmaxf(mxA.x, mxA.y);
    op[(size_t)KP * C + cB] = (sb.x + sb.y) * (1.0f / (float)HW) + fmaxf(mxB.x, mxB.y);
}

extern "C" void kernel_launch(void* const* d_in, const int* in_sizes, int n_in,
                              void* d_out, int out_size)
{
    const float* feat  = (const float*)d_in[0];
    const float* score = (const float*)d_in[1];
    const float* conf  = (const float*)d_in[2];
    float* out = (float*)d_out;

    const int N = in_sizes[2] / KP;                 // 256
    const int C = in_sizes[0] / ((size_t)N * HW);   // 2048

    float* out_feat = out;
    float* out_conf = out + (size_t)N * (KP + 1) * C;

    cudaFuncSetAttribute(horeid_kernel,
                         cudaFuncAttributeMaxDynamicSharedMemorySize, SMEM_BYTES);

    dim3 grid(C / CPB, N);
    horeid_kernel<<<grid, THREADS, SMEM_BYTES>>>(feat, score, conf,
                                                 out_feat, out_conf, C);
}